// round 14
// baseline (speedup 1.0000x reference)
#include <cuda_runtime.h>
#include <cuda_fp16.h>
#include <cstdint>
#include <cstddef>

// Shapes fixed: B=2048, A=128, D=5, Fa=62, Fb=6, C=256, Fin=68 (pad K0 to 80)
// CTA tile: M=64, N=256; 8 warps, warp w covers all 64 rows x cols [32w, 32w+32).
// fp16 scheme: A rounded to fp16, W pre-split hi+lo fp16 -> 2 MMA passes.
#define NT 256

// dynamic smem layout (bytes)
#define APL0     0            // A plane 0: [4 mt][16 kt][32 lane][16B] = 32KB
#define APL1     32768        // A plane 1: 32KB
#define WBUF_OFF 65536        // per-warp: 8 x (3 buffers x 2KB) = 48KB
#define WARP_WSZ 6144
#define SMEM_BYTES (65536 + 8*WARP_WSZ)   // 114688 = 112KB -> 2 CTAs/SM
#define HSTRIDE 80            // h0 staging row stride (floats) in gather kernel

#define NCHUNK 69             // layer0: 5 kt, layers1-4: 16 kt each

// weights, chunk-major, hi/lo interleaved per 16B:
// [chunk g(69)][warp(8)][ntl(4)][lane(32)][4 x u32: wh0 wh1 wl0 wl1] = 2KB/(g,warp)
__device__ __align__(16) uint32_t g_W2[NCHUNK*8*512];

// pre-gathered A fragments: [tile(4096)][mt(4)][kt(5)][lane(32)][4 x u32] = 10KB/tile
__device__ __align__(16) uint32_t g_A[4096*2560];

// ---------------- helpers ----------------
static __device__ __forceinline__ uint32_t smem_u32(const void* p){
    uint32_t a;
    asm("{ .reg .u64 t; cvta.to.shared.u64 t, %1; cvt.u32.u64 %0, t; }" : "=r"(a) : "l"(p));
    return a;
}

// pack two fp32 -> fp16x2 (lo = x, hi = y)
static __device__ __forceinline__ uint32_t pack2(float x, float y){
    uint32_t h;
    asm("cvt.rn.f16x2.f32 %0, %1, %2;" : "=r"(h) : "f"(y), "f"(x));
    return h;
}

#define MMA(d, a, b0, b1) \
    asm volatile("mma.sync.aligned.m16n8k16.row.col.f32.f16.f16.f32 " \
        "{%0,%1,%2,%3}, {%4,%5,%6,%7}, {%8,%9}, {%0,%1,%2,%3};" \
        : "+f"((d)[0]),"+f"((d)[1]),"+f"((d)[2]),"+f"((d)[3]) \
        : "r"((a)[0]),"r"((a)[1]),"r"((a)[2]),"r"((a)[3]), "r"(b0),"r"(b1))

#define LDS128(v, addr) \
    asm volatile("ld.shared.v4.b32 {%0,%1,%2,%3}, [%4];" \
        : "=r"((v)[0]),"=r"((v)[1]),"=r"((v)[2]),"=r"((v)[3]) : "r"(addr))

#define STS128(addr, v) \
    asm volatile("st.shared.v4.b32 [%0], {%1,%2,%3,%4};" \
        :: "r"(addr), "r"((v)[0]),"r"((v)[1]),"r"((v)[2]),"r"((v)[3]))

static __device__ __forceinline__ float ract(float x, float a0, float a1, float a2, float a3,
                                             float q0, float q1, float q2){
    float p = fmaf(fmaf(fmaf(a0, x, a1), x, a2), x, a3);
    float q = fmaf(fmaf(q0, x, q1), x, q2);    // q = 2.383 x^2 + 1 >= 1
    return __fdividef(p, q);
}

// per-warp: fetch this warp's 2KB B chunk for chunk g (single linear block)
static __device__ __forceinline__ void issue_chunk(int g, uint32_t sb, int wid, int lane){
    const uint32_t wb = sb + WBUF_OFF + (uint32_t)wid * WARP_WSZ
                      + (uint32_t)(g % 3) * 2048 + (uint32_t)lane * 16;
    const char* gp = (const char*)g_W2 + ((size_t)(g * 8 + wid)) * 2048 + (uint32_t)lane * 16;
#pragma unroll
    for (int i = 0; i < 4; i++)
        asm volatile("cp.async.ca.shared.global [%0], [%1], 16;"
                     :: "r"(wb + i * 512), "l"(gp + i * 512));
    asm volatile("cp.async.commit_group;" ::: "memory");
}

// ---------------- prep: W -> fp16 hi/lo B-fragment chunks ----------------
__global__ void prep_kernel(const float* __restrict__ W1, const float* __restrict__ W2,
                            const float* __restrict__ W3, const float* __restrict__ W4,
                            const float* __restrict__ W5)
{
    int i = blockIdx.x * blockDim.x + threadIdx.x;   // 5*16*32*32 = 81920
    if (i >= 5*16*32*32) return;
    const int lane = i & 31;
    const int nt   = (i >> 5) & 31;
    const int kt   = (i >> 10) & 15;
    const int l    = i >> 14;
    if (l == 0 && kt >= 5) return;                   // layer0 has only 5 kt chunks
    const float* W = (l == 0) ? W1 : (l == 1) ? W2 : (l == 2) ? W3 : (l == 3) ? W4 : W5;
    const int Kr = (l == 0) ? 68 : 256;
    const int tig = lane & 3, gid = lane >> 2;
    const int n  = nt * 8 + gid;
    const int k0 = kt * 16 + 2 * tig;

    float v[4], hi[4], lo[4];
#pragma unroll
    for (int r = 0; r < 4; r++){
        int k = k0 + (r >> 1) * 8 + (r & 1);         // k0, k0+1, k0+8, k0+9
        v[r] = (k < Kr) ? W[k * 256 + n] : 0.f;
        __half h = __float2half_rn(v[r]);
        hi[r] = __half2float(h);
        lo[r] = v[r] - hi[r];
    }
    uint32_t wh0 = pack2(hi[0], hi[1]), wh1 = pack2(hi[2], hi[3]);
    uint32_t wl0 = pack2(lo[0], lo[1]), wl1 = pack2(lo[2], lo[3]);

    const int g   = (l == 0) ? kt : 5 + (l - 1) * 16 + kt;
    const int w   = nt >> 2;                          // warp 0..7 owns 4 nt blocks
    const int ntl = nt & 3;
    const size_t base = (size_t)(g * 8 + w) * 512 + (size_t)ntl * 128 + (size_t)lane * 4;
    g_W2[base]     = wh0;  g_W2[base + 1] = wh1;      // hi pair
    g_W2[base + 2] = wl0;  g_W2[base + 3] = wl1;      // lo pair (same 16B unit)
}

// ---------------- gather: build fp16 A fragments for all tiles ----------------
__global__ __launch_bounds__(NT)
void gather_kernel(const float* __restrict__ atoms,
                   const float* __restrict__ bonds,
                   const int*   __restrict__ edges)
{
    __shared__ float hst[64 * HSTRIDE];
    const int tid  = threadIdx.x;
    const int lane = tid & 31;
    const int wid  = tid >> 5;
    const int tig  = lane & 3;
    const int gid  = lane >> 2;
    const int t    = blockIdx.x;

    const int batch = t >> 1;
    const int abase = (t & 1) * 64;
    const float* atom_b = atoms + (size_t)batch * 128 * 62;
    const float* bond_b = bonds + (size_t)batch * 128 * 30;
    const int*   edge_b = edges + (size_t)batch * 128 * 5;
    for (int idx = tid; idx < 64 * 80; idx += NT){
        const int r = idx / 80;
        const int f = idx - r * 80;
        const int a = abase + r;
        float v = 0.f;
        if (f < 62){
            v = atom_b[a * 62 + f];
#pragma unroll
            for (int d = 0; d < 5; d++){
                const int e = edge_b[a * 5 + d];
                if (e >= 0) v += atom_b[e * 62 + f];
            }
        } else if (f < 68){
            const int fb = f - 62;
#pragma unroll
            for (int d = 0; d < 5; d++)
                v += bond_b[(a * 5 + d) * 6 + fb];
        }
        hst[r * HSTRIDE + f] = v;
    }
    __syncthreads();

    // convert to fp16 A fragments (mt 0..3, kt 0..4) and store to g_A
    uint32_t* dst = g_A + (size_t)t * 2560;
    for (int task = wid; task < 20; task += 8){
        const int mt = task / 5;
        const int kt = task - mt * 5;
        const int r0 = mt * 16 + gid;
        const int c0 = kt * 16 + 2 * tig;
        float2 x0 = *(const float2*)&hst[r0 * HSTRIDE + c0];
        float2 x1 = *(const float2*)&hst[(r0 + 8) * HSTRIDE + c0];
        float2 x2 = *(const float2*)&hst[r0 * HSTRIDE + c0 + 8];
        float2 x3 = *(const float2*)&hst[(r0 + 8) * HSTRIDE + c0 + 8];
        uint4 u;
        u.x = pack2(x0.x, x0.y);
        u.y = pack2(x1.x, x1.y);
        u.z = pack2(x2.x, x2.y);
        u.w = pack2(x3.x, x3.y);
        *(uint4*)(dst + (size_t)(((mt * 5 + kt) * 32 + lane) * 4)) = u;
    }
}

// ---------------- main fused kernel ----------------
__global__ __launch_bounds__(NT, 2)
void drnfh_mma_kernel(const float* __restrict__ exist,
                      const float* __restrict__ b1, const float* __restrict__ b2,
                      const float* __restrict__ b3, const float* __restrict__ b4,
                      const float* __restrict__ b5,
                      const float* __restrict__ alphas, const float* __restrict__ betas,
                      float* __restrict__ out)
{
    extern __shared__ char smem[];
    const uint32_t sb = smem_u32(smem);

    const int tid  = threadIdx.x;
    const int lane = tid & 31;
    const int wid  = tid >> 5;                      // warp 0..7 -> cols [32w, 32w+32)
    const int tig  = lane & 3;
    const int gid  = lane >> 2;
    const int t    = blockIdx.x;                    // 64-row tile

    // ---- cp.async the pre-built A tile (10KB) into plane 0 ----
    {
        const char* src = (const char*)(g_A + (size_t)t * 2560);
#pragma unroll
        for (int i = 0; i < 3; i++){
            const int u = tid + NT * i;             // 640 16B units
            if (u < 640){
                const int mt   = u / 160;
                const int rest = u - mt * 160;      // kt*32 + lane
                const uint32_t dp = sb + APL0 + (uint32_t)(mt * 8192 + rest * 16);
                asm volatile("cp.async.ca.shared.global [%0], [%1], 16;"
                             :: "r"(dp), "l"(src + (size_t)u * 16));
            }
        }
        asm volatile("cp.async.commit_group;" ::: "memory");
    }
    issue_chunk(0, sb, wid, lane);
    issue_chunk(1, sb, wid, lane);

    // A plane visible to all threads: wait A group (W0/W1 may pend), then barrier
    asm volatile("cp.async.wait_group 2;" ::: "memory");
    __syncthreads();

    const float* bs[5] = { b1, b2, b3, b4, b5 };
    float acc[4][4][4];
    int g = 0;

#pragma unroll 1
    for (int l = 0; l < 5; l++){
        const int nkt = (l == 0) ? 5 : 16;
        const uint32_t pr = sb + ((l & 1) ? APL1 : APL0);        // read plane
        const uint32_t pw = sb + ((l & 1) ? APL0 : APL1);        // write plane (next layer)

#pragma unroll
        for (int i = 0; i < 4; i++)
#pragma unroll
            for (int j = 0; j < 4; j++)
#pragma unroll
                for (int r = 0; r < 4; r++) acc[i][j][r] = 0.f;

#pragma unroll 1
        for (int kt = 0; kt < nkt; kt++, g++){
            if (g == NCHUNK - 1)
                asm volatile("cp.async.wait_group 0;" ::: "memory");
            else
                asm volatile("cp.async.wait_group 1;" ::: "memory");
            if (g + 2 < NCHUNK) issue_chunk(g + 2, sb, wid, lane);

            const uint32_t wb = sb + WBUF_OFF + (uint32_t)wid * WARP_WSZ
                              + (uint32_t)(g % 3) * 2048;
            const uint32_t ao = (uint32_t)(kt * 512 + lane * 16);

            // B fragments: 4 nt blocks, {wh0,wh1,wl0,wl1} per 16B unit
            uint32_t bf[4][4];
#pragma unroll
            for (int nt = 0; nt < 4; nt++)
                LDS128(bf[nt], wb + (uint32_t)(nt * 512 + lane * 16));

            // A fragments (4 mt)
            uint32_t ah[4][4];
#pragma unroll
            for (int mt = 0; mt < 4; mt++)
                LDS128(ah[mt], pr + ao + (uint32_t)(mt * 8192));

            // pass hi
#pragma unroll
            for (int mt = 0; mt < 4; mt++)
#pragma unroll
                for (int nt = 0; nt < 4; nt++)
                    MMA(acc[mt][nt], ah[mt], bf[nt][0], bf[nt][1]);
            // pass lo
#pragma unroll
            for (int mt = 0; mt < 4; mt++)
#pragma unroll
                for (int nt = 0; nt < 4; nt++)
                    MMA(acc[mt][nt], ah[mt], bf[nt][2], bf[nt][3]);
        }

        // ---- layer epilogue (writes go to the OTHER plane; no pre-barrier needed) ----
        const float* bp = bs[l];
        const float a0 = __ldg(alphas + l*4 + 0), a1 = __ldg(alphas + l*4 + 1);
        const float a2 = __ldg(alphas + l*4 + 2), a3 = __ldg(alphas + l*4 + 3);
        const float q0 = __ldg(betas + l*3 + 0),  q1 = __ldg(betas + l*3 + 1);
        const float q2 = __ldg(betas + l*3 + 2);

        if (l < 4){
#pragma unroll
            for (int mt = 0; mt < 4; mt++){
#pragma unroll
                for (int jj = 0; jj < 4; jj += 2){
                    float x[8];
#pragma unroll
                    for (int p = 0; p < 2; p++){
                        const int n0 = (4 * wid + jj + p) * 8 + 2 * tig;
                        const float2 bb = *(const float2*)(bp + n0);
                        x[p*4+0] = ract(acc[mt][jj+p][0] + bb.x, a0,a1,a2,a3, q0,q1,q2);
                        x[p*4+1] = ract(acc[mt][jj+p][1] + bb.y, a0,a1,a2,a3, q0,q1,q2);
                        x[p*4+2] = ract(acc[mt][jj+p][2] + bb.x, a0,a1,a2,a3, q0,q1,q2);
                        x[p*4+3] = ract(acc[mt][jj+p][3] + bb.y, a0,a1,a2,a3, q0,q1,q2);
                    }
                    uint32_t ah2[4];
                    ah2[0] = pack2(x[0], x[1]);   // (row gid,   cols 2tig..)
                    ah2[1] = pack2(x[2], x[3]);   // (row gid+8)
                    ah2[2] = pack2(x[4], x[5]);   // cols +8
                    ah2[3] = pack2(x[6], x[7]);
                    const int ktn = 2 * wid + (jj >> 1);
                    const uint32_t off =
                        (uint32_t)(((mt * 16 + ktn) * 32 + lane) * 16);
                    STS128(pw + off, ah2);
                }
            }
            __syncthreads();   // new A plane visible before next layer's reads
        } else {
#pragma unroll
            for (int mt = 0; mt < 4; mt++){
                const int r0 = mt * 16 + gid;             // local row 0..63
                const float e0 = exist[t * 64 + r0];
                const float e1 = exist[t * 64 + r0 + 8];
#pragma unroll
                for (int j = 0; j < 4; j++){
                    const int n0 = (4 * wid + j) * 8 + 2 * tig;
                    const float2 bb = *(const float2*)(bp + n0);
                    float y0 = ract(acc[mt][j][0] + bb.x, a0,a1,a2,a3, q0,q1,q2) * e0;
                    float y1 = ract(acc[mt][j][1] + bb.y, a0,a1,a2,a3, q0,q1,q2) * e0;
                    float y2 = ract(acc[mt][j][2] + bb.x, a0,a1,a2,a3, q0,q1,q2) * e1;
                    float y3 = ract(acc[mt][j][3] + bb.y, a0,a1,a2,a3, q0,q1,q2) * e1;
                    *(float2*)(out + ((size_t)t * 64 + r0) * 256 + n0)     = make_float2(y0, y1);
                    *(float2*)(out + ((size_t)t * 64 + r0 + 8) * 256 + n0) = make_float2(y2, y3);
                }
            }
        }
    }
}

extern "C" void kernel_launch(void* const* d_in, const int* in_sizes, int n_in,
                              void* d_out, int out_size)
{
    const float* atoms = (const float*)d_in[0];
    const float* bonds = (const float*)d_in[1];
    const int*   edges = (const int*)  d_in[2];
    const float* exist = (const float*)d_in[3];
    const float* W1 = (const float*)d_in[4];
    const float* b1 = (const float*)d_in[5];
    const float* W2 = (const float*)d_in[6];
    const float* b2 = (const float*)d_in[7];
    const float* W3 = (const float*)d_in[8];
    const float* b3 = (const float*)d_in[9];
    const float* W4 = (const float*)d_in[10];
    const float* b4 = (const float*)d_in[11];
    const float* W5 = (const float*)d_in[12];
    const float* b5 = (const float*)d_in[13];
    const float* alphas = (const float*)d_in[14];
    const float* betas  = (const float*)d_in[15];
    float* out = (float*)d_out;

    const int M = out_size / 256;     // 262144 rows
    const int T = M / 64;             // 4096 tiles

    prep_kernel<<<(5*16*32*32 + 255) / 256, 256>>>(W1, W2, W3, W4, W5);
    gather_kernel<<<T, NT>>>(atoms, bonds, edges);

    cudaFuncSetAttribute(drnfh_mma_kernel,
                         cudaFuncAttributeMaxDynamicSharedMemorySize, SMEM_BYTES);
    drnfh_mma_kernel<<<T, NT, SMEM_BYTES>>>(
        exist, b1, b2, b3, b4, b5, alphas, betas, out);
}

// round 15
// speedup vs baseline: 1.4939x; 1.4939x over previous
#include <cuda_runtime.h>
#include <cuda_fp16.h>
#include <cstdint>
#include <cstddef>

// Shapes fixed: B=2048, A=128, D=5, Fa=62, Fb=6, C=256, Fin=68 (pad K0 to 80)
// CTA tile: M=64, N=256; 8 warps, warp w covers all 64 rows x cols [32w, 32w+32).
// fp16 scheme: A rounded to fp16, W pre-split hi+lo fp16 -> 2 MMA passes.
// A planes double-buffered: layer l reads plane l&1, epilogue writes plane (l+1)&1.
#define NT 256

// dynamic smem layout (bytes)
#define APL0     0            // A plane 0: [4 mt][16 kt][32 lane][16B] = 32KB
#define APL1     32768        // A plane 1: 32KB
#define WBUF_OFF 65536        // per-warp: 8 x (3 buffers x 2KB) = 48KB
#define WARP_WSZ 6144
#define SMEM_BYTES (65536 + 8*WARP_WSZ)   // 114688 = 112KB -> 2 CTAs/SM
#define HSTRIDE 80            // h0 staging row stride (floats), overlays WBUF

#define NCHUNK 69             // layer0: 5 kt, layers1-4: 16 kt each

// weights, chunk-major, hi/lo interleaved per 16B:
// [chunk g(69)][warp(8)][ntl(4)][lane(32)][4 x u32: wh0 wh1 wl0 wl1] = 2KB/(g,warp)
__device__ __align__(16) uint32_t g_W2[NCHUNK*8*512];

// ---------------- helpers ----------------
static __device__ __forceinline__ uint32_t smem_u32(const void* p){
    uint32_t a;
    asm("{ .reg .u64 t; cvta.to.shared.u64 t, %1; cvt.u32.u64 %0, t; }" : "=r"(a) : "l"(p));
    return a;
}

// pack two fp32 -> fp16x2 (lo = x, hi = y)
static __device__ __forceinline__ uint32_t pack2(float x, float y){
    uint32_t h;
    asm("cvt.rn.f16x2.f32 %0, %1, %2;" : "=r"(h) : "f"(y), "f"(x));
    return h;
}

#define MMA(d, a, b0, b1) \
    asm volatile("mma.sync.aligned.m16n8k16.row.col.f32.f16.f16.f32 " \
        "{%0,%1,%2,%3}, {%4,%5,%6,%7}, {%8,%9}, {%0,%1,%2,%3};" \
        : "+f"((d)[0]),"+f"((d)[1]),"+f"((d)[2]),"+f"((d)[3]) \
        : "r"((a)[0]),"r"((a)[1]),"r"((a)[2]),"r"((a)[3]), "r"(b0),"r"(b1))

#define LDS128(v, addr) \
    asm volatile("ld.shared.v4.b32 {%0,%1,%2,%3}, [%4];" \
        : "=r"((v)[0]),"=r"((v)[1]),"=r"((v)[2]),"=r"((v)[3]) : "r"(addr))

#define STS128(addr, v) \
    asm volatile("st.shared.v4.b32 [%0], {%1,%2,%3,%4};" \
        :: "r"(addr), "r"((v)[0]),"r"((v)[1]),"r"((v)[2]),"r"((v)[3]))

static __device__ __forceinline__ float ract(float x, float a0, float a1, float a2, float a3,
                                             float q0, float q1, float q2){
    float p = fmaf(fmaf(fmaf(a0, x, a1), x, a2), x, a3);
    float q = fmaf(fmaf(q0, x, q1), x, q2);    // q = 2.383 x^2 + 1 >= 1
    return __fdividef(p, q);
}

// per-warp: fetch this warp's 2KB B chunk for chunk g (single linear block)
static __device__ __forceinline__ void issue_chunk(int g, uint32_t sb, int wid, int lane){
    const uint32_t wb = sb + WBUF_OFF + (uint32_t)wid * WARP_WSZ
                      + (uint32_t)(g % 3) * 2048 + (uint32_t)lane * 16;
    const char* gp = (const char*)g_W2 + ((size_t)(g * 8 + wid)) * 2048 + (uint32_t)lane * 16;
#pragma unroll
    for (int i = 0; i < 4; i++)
        asm volatile("cp.async.ca.shared.global [%0], [%1], 16;"
                     :: "r"(wb + i * 512), "l"(gp + i * 512));
    asm volatile("cp.async.commit_group;" ::: "memory");
}

// ---------------- prep: W -> fp16 hi/lo B-fragment chunks ----------------
__global__ void prep_kernel(const float* __restrict__ W1, const float* __restrict__ W2,
                            const float* __restrict__ W3, const float* __restrict__ W4,
                            const float* __restrict__ W5)
{
    int i = blockIdx.x * blockDim.x + threadIdx.x;   // 5*16*32*32 = 81920
    if (i >= 5*16*32*32) return;
    const int lane = i & 31;
    const int nt   = (i >> 5) & 31;
    const int kt   = (i >> 10) & 15;
    const int l    = i >> 14;
    if (l == 0 && kt >= 5) return;                   // layer0 has only 5 kt chunks
    const float* W = (l == 0) ? W1 : (l == 1) ? W2 : (l == 2) ? W3 : (l == 3) ? W4 : W5;
    const int Kr = (l == 0) ? 68 : 256;
    const int tig = lane & 3, gid = lane >> 2;
    const int n  = nt * 8 + gid;
    const int k0 = kt * 16 + 2 * tig;

    float v[4], hi[4], lo[4];
#pragma unroll
    for (int r = 0; r < 4; r++){
        int k = k0 + (r >> 1) * 8 + (r & 1);         // k0, k0+1, k0+8, k0+9
        v[r] = (k < Kr) ? W[k * 256 + n] : 0.f;
        __half h = __float2half_rn(v[r]);
        hi[r] = __half2float(h);
        lo[r] = v[r] - hi[r];
    }
    uint32_t wh0 = pack2(hi[0], hi[1]), wh1 = pack2(hi[2], hi[3]);
    uint32_t wl0 = pack2(lo[0], lo[1]), wl1 = pack2(lo[2], lo[3]);

    const int g   = (l == 0) ? kt : 5 + (l - 1) * 16 + kt;
    const int w   = nt >> 2;                          // warp 0..7 owns 4 nt blocks
    const int ntl = nt & 3;
    const size_t base = (size_t)(g * 8 + w) * 512 + (size_t)ntl * 128 + (size_t)lane * 4;
    g_W2[base]     = wh0;  g_W2[base + 1] = wh1;      // hi pair
    g_W2[base + 2] = wl0;  g_W2[base + 3] = wl1;      // lo pair (same 16B unit)
}

// ---------------- main fused kernel ----------------
__global__ __launch_bounds__(NT, 2)
void drnfh_mma_kernel(const float* __restrict__ atoms,
                      const float* __restrict__ bonds,
                      const int*   __restrict__ edges,
                      const float* __restrict__ exist,
                      const float* __restrict__ b1, const float* __restrict__ b2,
                      const float* __restrict__ b3, const float* __restrict__ b4,
                      const float* __restrict__ b5,
                      const float* __restrict__ alphas, const float* __restrict__ betas,
                      float* __restrict__ out)
{
    extern __shared__ char smem[];
    const uint32_t sb = smem_u32(smem);
    float* hst = (float*)(smem + WBUF_OFF);         // h0 staging overlays W buffers

    const int tid  = threadIdx.x;
    const int lane = tid & 31;
    const int wid  = tid >> 5;                      // warp 0..7 -> cols [32w, 32w+32)
    const int tig  = lane & 3;
    const int gid  = lane >> 2;
    const int t    = blockIdx.x;                    // 64-row tile; batch = t>>1

    // ---- build h0 fp32 (64 x 80, zero-padded) ----
    {
        const int batch = t >> 1;
        const int abase = (t & 1) * 64;
        const float* atom_b = atoms + (size_t)batch * 128 * 62;
        const float* bond_b = bonds + (size_t)batch * 128 * 30;
        const int*   edge_b = edges + (size_t)batch * 128 * 5;
        for (int idx = tid; idx < 64 * 80; idx += NT){
            const int r = idx / 80;
            const int f = idx - r * 80;
            const int a = abase + r;
            float v = 0.f;
            if (f < 62){
                v = atom_b[a * 62 + f];
#pragma unroll
                for (int d = 0; d < 5; d++){
                    const int e = edge_b[a * 5 + d];
                    if (e >= 0) v += atom_b[e * 62 + f];
                }
            } else if (f < 68){
                const int fb = f - 62;
#pragma unroll
                for (int d = 0; d < 5; d++)
                    v += bond_b[(a * 5 + d) * 6 + fb];
            }
            hst[r * HSTRIDE + f] = v;
        }
    }
    __syncthreads();

    // ---- convert h0 into fp16 A fragment plane 0 (mt 0..3, kt 0..4) ----
    for (int task = wid; task < 20; task += 8){
        const int mt = task / 5;
        const int kt = task - mt * 5;
        const int r0 = mt * 16 + gid;
        const int c0 = kt * 16 + 2 * tig;
        float2 x0 = *(const float2*)&hst[r0 * HSTRIDE + c0];
        float2 x1 = *(const float2*)&hst[(r0 + 8) * HSTRIDE + c0];
        float2 x2 = *(const float2*)&hst[r0 * HSTRIDE + c0 + 8];
        float2 x3 = *(const float2*)&hst[(r0 + 8) * HSTRIDE + c0 + 8];
        uint32_t ah[4];
        ah[0] = pack2(x0.x, x0.y);
        ah[1] = pack2(x1.x, x1.y);
        ah[2] = pack2(x2.x, x2.y);
        ah[3] = pack2(x3.x, x3.y);
        const uint32_t off = (uint32_t)(((mt * 16 + kt) * 32 + lane) * 16);
        STS128(sb + APL0 + off, ah);
    }
    __syncthreads();   // hst reads done; WBUF region reusable; plane 0 visible

    issue_chunk(0, sb, wid, lane);
    issue_chunk(1, sb, wid, lane);

    const float* bs[5] = { b1, b2, b3, b4, b5 };
    float acc[4][4][4];
    int g = 0;

#pragma unroll 1
    for (int l = 0; l < 5; l++){
        const int nkt = (l == 0) ? 5 : 16;
        const uint32_t pr = sb + ((l & 1) ? APL1 : APL0);        // read plane
        const uint32_t pw = sb + ((l & 1) ? APL0 : APL1);        // write plane (next layer)

#pragma unroll
        for (int i = 0; i < 4; i++)
#pragma unroll
            for (int j = 0; j < 4; j++)
#pragma unroll
                for (int r = 0; r < 4; r++) acc[i][j][r] = 0.f;

#pragma unroll 1
        for (int kt = 0; kt < nkt; kt++, g++){
            if (g == NCHUNK - 1)
                asm volatile("cp.async.wait_group 0;" ::: "memory");
            else
                asm volatile("cp.async.wait_group 1;" ::: "memory");
            if (g + 2 < NCHUNK) issue_chunk(g + 2, sb, wid, lane);

            const uint32_t wb = sb + WBUF_OFF + (uint32_t)wid * WARP_WSZ
                              + (uint32_t)(g % 3) * 2048;
            const uint32_t ao = (uint32_t)(kt * 512 + lane * 16);

            // B fragments: 4 nt blocks, {wh0,wh1,wl0,wl1} per 16B unit
            uint32_t bf[4][4];
#pragma unroll
            for (int nt = 0; nt < 4; nt++)
                LDS128(bf[nt], wb + (uint32_t)(nt * 512 + lane * 16));

            // A fragments (4 mt)
            uint32_t ah[4][4];
#pragma unroll
            for (int mt = 0; mt < 4; mt++)
                LDS128(ah[mt], pr + ao + (uint32_t)(mt * 8192));

            // pass hi
#pragma unroll
            for (int mt = 0; mt < 4; mt++)
#pragma unroll
                for (int nt = 0; nt < 4; nt++)
                    MMA(acc[mt][nt], ah[mt], bf[nt][0], bf[nt][1]);
            // pass lo
#pragma unroll
            for (int mt = 0; mt < 4; mt++)
#pragma unroll
                for (int nt = 0; nt < 4; nt++)
                    MMA(acc[mt][nt], ah[mt], bf[nt][2], bf[nt][3]);
        }

        // ---- layer epilogue (writes to the OTHER plane; no pre-barrier) ----
        const float* bp = bs[l];
        const float a0 = __ldg(alphas + l*4 + 0), a1 = __ldg(alphas + l*4 + 1);
        const float a2 = __ldg(alphas + l*4 + 2), a3 = __ldg(alphas + l*4 + 3);
        const float q0 = __ldg(betas + l*3 + 0),  q1 = __ldg(betas + l*3 + 1);
        const float q2 = __ldg(betas + l*3 + 2);

        if (l < 4){
#pragma unroll
            for (int mt = 0; mt < 4; mt++){
#pragma unroll
                for (int jj = 0; jj < 4; jj += 2){
                    float x[8];
#pragma unroll
                    for (int p = 0; p < 2; p++){
                        const int n0 = (4 * wid + jj + p) * 8 + 2 * tig;
                        const float2 bb = *(const float2*)(bp + n0);
                        x[p*4+0] = ract(acc[mt][jj+p][0] + bb.x, a0,a1,a2,a3, q0,q1,q2);
                        x[p*4+1] = ract(acc[mt][jj+p][1] + bb.y, a0,a1,a2,a3, q0,q1,q2);
                        x[p*4+2] = ract(acc[mt][jj+p][2] + bb.x, a0,a1,a2,a3, q0,q1,q2);
                        x[p*4+3] = ract(acc[mt][jj+p][3] + bb.y, a0,a1,a2,a3, q0,q1,q2);
                    }
                    uint32_t ah2[4];
                    ah2[0] = pack2(x[0], x[1]);   // (row gid,   cols 2tig..)
                    ah2[1] = pack2(x[2], x[3]);   // (row gid+8)
                    ah2[2] = pack2(x[4], x[5]);   // cols +8
                    ah2[3] = pack2(x[6], x[7]);
                    const int ktn = 2 * wid + (jj >> 1);
                    const uint32_t off =
                        (uint32_t)(((mt * 16 + ktn) * 32 + lane) * 16);
                    STS128(pw + off, ah2);
                }
            }
            __syncthreads();   // new A plane visible before next layer's reads
        } else {
#pragma unroll
            for (int mt = 0; mt < 4; mt++){
                const int r0 = mt * 16 + gid;             // local row 0..63
                const float e0 = exist[t * 64 + r0];
                const float e1 = exist[t * 64 + r0 + 8];
#pragma unroll
                for (int j = 0; j < 4; j++){
                    const int n0 = (4 * wid + j) * 8 + 2 * tig;
                    const float2 bb = *(const float2*)(bp + n0);
                    float y0 = ract(acc[mt][j][0] + bb.x, a0,a1,a2,a3, q0,q1,q2) * e0;
                    float y1 = ract(acc[mt][j][1] + bb.y, a0,a1,a2,a3, q0,q1,q2) * e0;
                    float y2 = ract(acc[mt][j][2] + bb.x, a0,a1,a2,a3, q0,q1,q2) * e1;
                    float y3 = ract(acc[mt][j][3] + bb.y, a0,a1,a2,a3, q0,q1,q2) * e1;
                    *(float2*)(out + ((size_t)t * 64 + r0) * 256 + n0)     = make_float2(y0, y1);
                    *(float2*)(out + ((size_t)t * 64 + r0 + 8) * 256 + n0) = make_float2(y2, y3);
                }
            }
        }
    }
}

extern "C" void kernel_launch(void* const* d_in, const int* in_sizes, int n_in,
                              void* d_out, int out_size)
{
    const float* atoms = (const float*)d_in[0];
    const float* bonds = (const float*)d_in[1];
    const int*   edges = (const int*)  d_in[2];
    const float* exist = (const float*)d_in[3];
    const float* W1 = (const float*)d_in[4];
    const float* b1 = (const float*)d_in[5];
    const float* W2 = (const float*)d_in[6];
    const float* b2 = (const float*)d_in[7];
    const float* W3 = (const float*)d_in[8];
    const float* b3 = (const float*)d_in[9];
    const float* W4 = (const float*)d_in[10];
    const float* b4 = (const float*)d_in[11];
    const float* W5 = (const float*)d_in[12];
    const float* b5 = (const float*)d_in[13];
    const float* alphas = (const float*)d_in[14];
    const float* betas  = (const float*)d_in[15];
    float* out = (float*)d_out;

    const int M = out_size / 256;     // 262144 rows
    const int T = M / 64;             // 4096 CTAs

    prep_kernel<<<(5*16*32*32 + 255) / 256, 256>>>(W1, W2, W3, W4, W5);

    cudaFuncSetAttribute(drnfh_mma_kernel,
                         cudaFuncAttributeMaxDynamicSharedMemorySize, SMEM_BYTES);
    drnfh_mma_kernel<<<T, NT, SMEM_BYTES>>>(
        atoms, bonds, edges, exist,
        b1, b2, b3, b4, b5, alphas, betas, out);
}

// round 16
// speedup vs baseline: 1.6710x; 1.1185x over previous
#include <cuda_runtime.h>
#include <cuda_fp16.h>
#include <cstdint>
#include <cstddef>

// Shapes fixed: B=2048, A=128, D=5, Fa=62, Fb=6, C=256, Fin=68 (pad K0 to 80)
// CTA tile: M=64, N=256; 8 warps, warp w covers all 64 rows x cols [32w, 32w+32).
// fp16 scheme: A rounded to fp16, W pre-split hi+lo fp16 -> 2 MMA passes.
// B operands: direct LDG.128 from L2-resident g_W2 into registers, 1-chunk prefetch.
#define NT 256

// dynamic smem layout (bytes)
#define APL0     0            // A plane: [4 mt][16 kt][32 lane][16B] = 32KB
#define HST_OFF  32768        // h0 staging: 64*80*4 = 20.5KB (prologue only)
#define SMEM_BYTES (32768 + 64*80*4)   // 53248
#define HSTRIDE 80

#define NCHUNK 69             // layer0: 5 kt, layers1-4: 16 kt each

// weights, chunk-major, hi/lo interleaved per 16B:
// [chunk g(69)][warp(8)][ntl(4)][lane(32)][4 x u32: wh0 wh1 wl0 wl1] = 2KB/(g,warp)
__device__ __align__(16) uint32_t g_W2[NCHUNK*8*512];

// ---------------- helpers ----------------
static __device__ __forceinline__ uint32_t smem_u32(const void* p){
    uint32_t a;
    asm("{ .reg .u64 t; cvta.to.shared.u64 t, %1; cvt.u32.u64 %0, t; }" : "=r"(a) : "l"(p));
    return a;
}

// pack two fp32 -> fp16x2 (lo = x, hi = y)
static __device__ __forceinline__ uint32_t pack2(float x, float y){
    uint32_t h;
    asm("cvt.rn.f16x2.f32 %0, %1, %2;" : "=r"(h) : "f"(y), "f"(x));
    return h;
}

#define MMA(d, a, b0, b1) \
    asm volatile("mma.sync.aligned.m16n8k16.row.col.f32.f16.f16.f32 " \
        "{%0,%1,%2,%3}, {%4,%5,%6,%7}, {%8,%9}, {%0,%1,%2,%3};" \
        : "+f"((d)[0]),"+f"((d)[1]),"+f"((d)[2]),"+f"((d)[3]) \
        : "r"((a)[0]),"r"((a)[1]),"r"((a)[2]),"r"((a)[3]), "r"(b0),"r"(b1))

#define LDS128(v, addr) \
    asm volatile("ld.shared.v4.b32 {%0,%1,%2,%3}, [%4];" \
        : "=r"((v)[0]),"=r"((v)[1]),"=r"((v)[2]),"=r"((v)[3]) : "r"(addr))

#define STS128(addr, v) \
    asm volatile("st.shared.v4.b32 [%0], {%1,%2,%3,%4};" \
        :: "r"(addr), "r"((v)[0]),"r"((v)[1]),"r"((v)[2]),"r"((v)[3]))

static __device__ __forceinline__ float ract(float x, float a0, float a1, float a2, float a3,
                                             float q0, float q1, float q2){
    float p = fmaf(fmaf(fmaf(a0, x, a1), x, a2), x, a3);
    float q = fmaf(fmaf(q0, x, q1), x, q2);    // q = 2.383 x^2 + 1 >= 1
    return __fdividef(p, q);
}

// ---------------- prep: W -> fp16 hi/lo B-fragment chunks ----------------
__global__ void prep_kernel(const float* __restrict__ W1, const float* __restrict__ W2,
                            const float* __restrict__ W3, const float* __restrict__ W4,
                            const float* __restrict__ W5)
{
    int i = blockIdx.x * blockDim.x + threadIdx.x;   // 5*16*32*32 = 81920
    if (i >= 5*16*32*32) return;
    const int lane = i & 31;
    const int nt   = (i >> 5) & 31;
    const int kt   = (i >> 10) & 15;
    const int l    = i >> 14;
    if (l == 0 && kt >= 5) return;                   // layer0 has only 5 kt chunks
    const float* W = (l == 0) ? W1 : (l == 1) ? W2 : (l == 2) ? W3 : (l == 3) ? W4 : W5;
    const int Kr = (l == 0) ? 68 : 256;
    const int tig = lane & 3, gid = lane >> 2;
    const int n  = nt * 8 + gid;
    const int k0 = kt * 16 + 2 * tig;

    float v[4], hi[4], lo[4];
#pragma unroll
    for (int r = 0; r < 4; r++){
        int k = k0 + (r >> 1) * 8 + (r & 1);         // k0, k0+1, k0+8, k0+9
        v[r] = (k < Kr) ? W[k * 256 + n] : 0.f;
        __half h = __float2half_rn(v[r]);
        hi[r] = __half2float(h);
        lo[r] = v[r] - hi[r];
    }
    uint32_t wh0 = pack2(hi[0], hi[1]), wh1 = pack2(hi[2], hi[3]);
    uint32_t wl0 = pack2(lo[0], lo[1]), wl1 = pack2(lo[2], lo[3]);

    const int g   = (l == 0) ? kt : 5 + (l - 1) * 16 + kt;
    const int w   = nt >> 2;                          // warp 0..7 owns 4 nt blocks
    const int ntl = nt & 3;
    const size_t base = (size_t)(g * 8 + w) * 512 + (size_t)ntl * 128 + (size_t)lane * 4;
    g_W2[base]     = wh0;  g_W2[base + 1] = wh1;      // hi pair
    g_W2[base + 2] = wl0;  g_W2[base + 3] = wl1;      // lo pair (same 16B unit)
}

// ---------------- main fused kernel ----------------
__global__ __launch_bounds__(NT, 2)
void drnfh_mma_kernel(const float* __restrict__ atoms,
                      const float* __restrict__ bonds,
                      const int*   __restrict__ edges,
                      const float* __restrict__ exist,
                      const float* __restrict__ b1, const float* __restrict__ b2,
                      const float* __restrict__ b3, const float* __restrict__ b4,
                      const float* __restrict__ b5,
                      const float* __restrict__ alphas, const float* __restrict__ betas,
                      float* __restrict__ out)
{
    extern __shared__ char smem[];
    const uint32_t sb = smem_u32(smem);
    float* hst = (float*)(smem + HST_OFF);

    const int tid  = threadIdx.x;
    const int lane = tid & 31;
    const int wid  = tid >> 5;                      // warp 0..7 -> cols [32w, 32w+32)
    const int tig  = lane & 3;
    const int gid  = lane >> 2;
    const int t    = blockIdx.x;                    // 64-row tile; batch = t>>1

    // ---- prefetch B chunk 0 into registers (hides under the gather) ----
    // uint4 units: per (g,warp) block = 128 uint4; ntl stride = 32; chunk stride = 1024
    const uint4* gp = (const uint4*)g_W2 + (size_t)wid * 128 + lane;
    uint4 nb[4];
    nb[0] = __ldg(gp);  nb[1] = __ldg(gp + 32);
    nb[2] = __ldg(gp + 64);  nb[3] = __ldg(gp + 96);

    // ---- build h0 fp32 (64 x 80, zero-padded) ----
    {
        const int batch = t >> 1;
        const int abase = (t & 1) * 64;
        const float* atom_b = atoms + (size_t)batch * 128 * 62;
        const float* bond_b = bonds + (size_t)batch * 128 * 30;
        const int*   edge_b = edges + (size_t)batch * 128 * 5;
        for (int idx = tid; idx < 64 * 80; idx += NT){
            const int r = idx / 80;
            const int f = idx - r * 80;
            const int a = abase + r;
            float v = 0.f;
            if (f < 62){
                v = atom_b[a * 62 + f];
#pragma unroll
                for (int d = 0; d < 5; d++){
                    const int e = edge_b[a * 5 + d];
                    if (e >= 0) v += atom_b[e * 62 + f];
                }
            } else if (f < 68){
                const int fb = f - 62;
#pragma unroll
                for (int d = 0; d < 5; d++)
                    v += bond_b[(a * 5 + d) * 6 + fb];
            }
            hst[r * HSTRIDE + f] = v;
        }
    }
    __syncthreads();

    // ---- convert h0 into fp16 A fragment plane (mt 0..3, kt 0..4) ----
    for (int task = wid; task < 20; task += 8){
        const int mt = task / 5;
        const int kt = task - mt * 5;
        const int r0 = mt * 16 + gid;
        const int c0 = kt * 16 + 2 * tig;
        float2 x0 = *(const float2*)&hst[r0 * HSTRIDE + c0];
        float2 x1 = *(const float2*)&hst[(r0 + 8) * HSTRIDE + c0];
        float2 x2 = *(const float2*)&hst[r0 * HSTRIDE + c0 + 8];
        float2 x3 = *(const float2*)&hst[(r0 + 8) * HSTRIDE + c0 + 8];
        uint32_t ah[4];
        ah[0] = pack2(x0.x, x0.y);
        ah[1] = pack2(x1.x, x1.y);
        ah[2] = pack2(x2.x, x2.y);
        ah[3] = pack2(x3.x, x3.y);
        const uint32_t off = (uint32_t)(((mt * 16 + kt) * 32 + lane) * 16);
        STS128(sb + APL0 + off, ah);
    }
    __syncthreads();   // A plane visible

    const float* bs[5] = { b1, b2, b3, b4, b5 };
    float acc[4][4][4];
    int g = 0;

#pragma unroll 1
    for (int l = 0; l < 5; l++){
        const int nkt = (l == 0) ? 5 : 16;

#pragma unroll
        for (int i = 0; i < 4; i++)
#pragma unroll
            for (int j = 0; j < 4; j++)
#pragma unroll
                for (int r = 0; r < 4; r++) acc[i][j][r] = 0.f;

#pragma unroll 1
        for (int kt = 0; kt < nkt; kt++, g++){
            // rotate prefetched B into current; prefetch next chunk
            uint4 cb[4];
#pragma unroll
            for (int nt = 0; nt < 4; nt++) cb[nt] = nb[nt];
            gp += 1024;
            if (g + 1 < NCHUNK){
                nb[0] = __ldg(gp);  nb[1] = __ldg(gp + 32);
                nb[2] = __ldg(gp + 64);  nb[3] = __ldg(gp + 96);
            }

            // A fragments (4 mt)
            const uint32_t ao = (uint32_t)(kt * 512 + lane * 16);
            uint32_t ah[4][4];
#pragma unroll
            for (int mt = 0; mt < 4; mt++)
                LDS128(ah[mt], sb + APL0 + ao + (uint32_t)(mt * 8192));

            // pass hi
#pragma unroll
            for (int mt = 0; mt < 4; mt++)
#pragma unroll
                for (int nt = 0; nt < 4; nt++)
                    MMA(acc[mt][nt], ah[mt], cb[nt].x, cb[nt].y);
            // pass lo
#pragma unroll
            for (int mt = 0; mt < 4; mt++)
#pragma unroll
                for (int nt = 0; nt < 4; nt++)
                    MMA(acc[mt][nt], ah[mt], cb[nt].z, cb[nt].w);
        }

        // ---- layer epilogue ----
        __syncthreads();   // all warps done reading this layer's A plane
        const float* bp = bs[l];
        const float a0 = __ldg(alphas + l*4 + 0), a1 = __ldg(alphas + l*4 + 1);
        const float a2 = __ldg(alphas + l*4 + 2), a3 = __ldg(alphas + l*4 + 3);
        const float q0 = __ldg(betas + l*3 + 0),  q1 = __ldg(betas + l*3 + 1);
        const float q2 = __ldg(betas + l*3 + 2);

        if (l < 4){
#pragma unroll
            for (int mt = 0; mt < 4; mt++){
#pragma unroll
                for (int jj = 0; jj < 4; jj += 2){
                    float x[8];
#pragma unroll
                    for (int p = 0; p < 2; p++){
                        const int n0 = (4 * wid + jj + p) * 8 + 2 * tig;
                        const float2 bb = *(const float2*)(bp + n0);
                        x[p*4+0] = ract(acc[mt][jj+p][0] + bb.x, a0,a1,a2,a3, q0,q1,q2);
                        x[p*4+1] = ract(acc[mt][jj+p][1] + bb.y, a0,a1,a2,a3, q0,q1,q2);
                        x[p*4+2] = ract(acc[mt][jj+p][2] + bb.x, a0,a1,a2,a3, q0,q1,q2);
                        x[p*4+3] = ract(acc[mt][jj+p][3] + bb.y, a0,a1,a2,a3, q0,q1,q2);
                    }
                    uint32_t ah2[4];
                    ah2[0] = pack2(x[0], x[1]);   // (row gid,   cols 2tig..)
                    ah2[1] = pack2(x[2], x[3]);   // (row gid+8)
                    ah2[2] = pack2(x[4], x[5]);   // cols +8
                    ah2[3] = pack2(x[6], x[7]);
                    const int ktn = 2 * wid + (jj >> 1);
                    const uint32_t off =
                        (uint32_t)(((mt * 16 + ktn) * 32 + lane) * 16);
                    STS128(sb + APL0 + off, ah2);
                }
            }
            __syncthreads();   // new A plane visible before next layer's reads
        } else {
#pragma unroll
            for (int mt = 0; mt < 4; mt++){
                const int r0 = mt * 16 + gid;             // local row 0..63
                const float e0 = exist[t * 64 + r0];
                const float e1 = exist[t * 64 + r0 + 8];
#pragma unroll
                for (int j = 0; j < 4; j++){
                    const int n0 = (4 * wid + j) * 8 + 2 * tig;
                    const float2 bb = *(const float2*)(bp + n0);
                    float y0 = ract(acc[mt][j][0] + bb.x, a0,a1,a2,a3, q0,q1,q2) * e0;
                    float y1 = ract(acc[mt][j][1] + bb.y, a0,a1,a2,a3, q0,q1,q2) * e0;
                    float y2 = ract(acc[mt][j][2] + bb.x, a0,a1,a2,a3, q0,q1,q2) * e1;
                    float y3 = ract(acc[mt][j][3] + bb.y, a0,a1,a2,a3, q0,q1,q2) * e1;
                    *(float2*)(out + ((size_t)t * 64 + r0) * 256 + n0)     = make_float2(y0, y1);
                    *(float2*)(out + ((size_t)t * 64 + r0 + 8) * 256 + n0) = make_float2(y2, y3);
                }
            }
        }
    }
}

extern "C" void kernel_launch(void* const* d_in, const int* in_sizes, int n_in,
                              void* d_out, int out_size)
{
    const float* atoms = (const float*)d_in[0];
    const float* bonds = (const float*)d_in[1];
    const int*   edges = (const int*)  d_in[2];
    const float* exist = (const float*)d_in[3];
    const float* W1 = (const float*)d_in[4];
    const float* b1 = (const float*)d_in[5];
    const float* W2 = (const float*)d_in[6];
    const float* b2 = (const float*)d_in[7];
    const float* W3 = (const float*)d_in[8];
    const float* b3 = (const float*)d_in[9];
    const float* W4 = (const float*)d_in[10];
    const float* b4 = (const float*)d_in[11];
    const float* W5 = (const float*)d_in[12];
    const float* b5 = (const float*)d_in[13];
    const float* alphas = (const float*)d_in[14];
    const float* betas  = (const float*)d_in[15];
    float* out = (float*)d_out;

    const int M = out_size / 256;     // 262144 rows
    const int T = M / 64;             // 4096 CTAs

    prep_kernel<<<(5*16*32*32 + 255) / 256, 256>>>(W1, W2, W3, W4, W5);

    cudaFuncSetAttribute(drnfh_mma_kernel,
                         cudaFuncAttributeMaxDynamicSharedMemorySize, SMEM_BYTES);
    drnfh_mma_kernel<<<T, NT, SMEM_BYTES>>>(
        atoms, bonds, edges, exist,
        b1, b2, b3, b4, b5, alphas, betas, out);
}